// round 4
// baseline (speedup 1.0000x reference)
#include <cuda_runtime.h>

// Problem constants
#define NN      100000
#define EE      1600000
#define CC      25000          // N / PF
#define DIN     128
#define DINTER  144
#define BITWORDS 19531250      // ceil(C*C / 32) = 625,000,000 / 32 (exact)
#define NB_BM   4769           // ceil(BITWORDS / 4096)

// Output layout (float32, flattened tuple in return order)
#define XN_OFF  0              // x_new        [C][128]  = 3,200,000
#define NP_OFF  3200000        // new_pos      [C][3]    =    75,000
#define EI0_OFF 3275000        // new_edge_index[0][E]   = 1,600,000
#define EI1_OFF 4875000        // new_edge_index[1][E]   = 1,600,000
#define EAT_OFF 6475000        // new_edge_attr[E][3]    = 4,800,000
#define NB_OFF  11275000       // new_batch    [C]       =    25,000
// total = 11,300,000

// ---------------- static device scratch (no allocations allowed) ----------------
__device__ __align__(16) unsigned g_bitmap[BITWORDS];   // 78.1 MB
__device__ int   g_cnt[CC];
__device__ int   g_off[CC + 1];
__device__ int   g_cur[CC];
__device__ int   g_srcsorted[EE];                       // src ids sorted by dst-cluster
__device__ float g_aggea[CC * 3];                       // per-cluster edge_attr sums
__device__ float g_r[CC * 3];                           // per-cluster pos residual
__device__ float g_Wcomb[DIN * 128];                    // W_conv[:,16:] @ W_gather
__device__ float g_Wecomb[3 * 128];                     // W_edge[:,16:] @ W_gather
__device__ int   g_bsum[NB_BM];
__device__ int   g_boff[NB_BM];

// ---------------- kernels ----------------

// Zero bitmap, counters, per-cluster accumulators, and the edge-output region of d_out
__global__ void k_zero(float* __restrict__ dout) {
    int tid = blockIdx.x * blockDim.x + threadIdx.x;
    int stride = gridDim.x * blockDim.x;
    uint4 z4 = make_uint4(0u, 0u, 0u, 0u);
    uint4* bm4 = (uint4*)g_bitmap;
    const int n4 = BITWORDS / 4;            // 4,882,812 (covers 19,531,248 words)
    for (int i = tid; i < n4; i += stride) bm4[i] = z4;
    if (tid < 2) g_bitmap[19531248 + tid] = 0u;   // tail words
    for (int i = tid; i < CC; i += stride) g_cnt[i] = 0;
    for (int i = tid; i < CC * 3; i += stride) g_aggea[i] = 0.0f;
    float4 f4 = make_float4(0.f, 0.f, 0.f, 0.f);
    float4* d4 = (float4*)(dout + EI0_OFF);  // 8,000,000 floats (edge idx + attr), 16B aligned
    for (int i = tid; i < 2000000; i += stride) d4[i] = f4;
}

// Fold W_gather into the feat-part of W_conv / W_edge (tiny GEMMs, recomputed each call)
__global__ void k_wcomb(const float* __restrict__ Wconv,
                        const float* __restrict__ Wedge,
                        const float* __restrict__ Wg) {
    int b = blockIdx.x;      // 0..130
    int j = threadIdx.x;     // 0..127
    if (b < 128) {
        float acc = 0.0f;
        #pragma unroll 8
        for (int t = 0; t < 128; t++)
            acc += Wconv[b * DINTER + 16 + t] * Wg[t * 128 + j];
        g_Wcomb[b * 128 + j] = acc;
    } else {
        int a = b - 128;     // 0..2
        float acc = 0.0f;
        #pragma unroll 8
        for (int t = 0; t < 128; t++)
            acc += Wedge[a * DINTER + 16 + t] * Wg[t * 128 + j];
        g_Wecomb[a * 128 + j] = acc;
    }
}

// Pass over edges: histogram by dst-cluster, set bitmap bit for enc, accumulate edge_attr
__global__ void k_edge1(const int* __restrict__ ei, const float* __restrict__ ea) {
    int e = blockIdx.x * blockDim.x + threadIdx.x;
    if (e >= EE) return;
    int s = ei[e];
    int d = ei[EE + e];
    int c = d >> 2;
    atomicAdd(&g_cnt[c], 1);
    int enc = (s >> 2) * CC + c;                      // < 625,000,000, fits int32
    atomicOr(&g_bitmap[enc >> 5], 1u << (enc & 31));
    float a0 = ea[e * 3 + 0], a1 = ea[e * 3 + 1], a2 = ea[e * 3 + 2];
    atomicAdd(&g_aggea[c * 3 + 0], a0);
    atomicAdd(&g_aggea[c * 3 + 1], a1);
    atomicAdd(&g_aggea[c * 3 + 2], a2);
}

// Single-block exclusive scan helper (n up to ~26k, 1024 threads)
__device__ void scan_dev(const int* in, int* out, int* out2, int n, int writeTotal) {
    __shared__ int sd[1024];
    __shared__ int s_base;
    int tid = threadIdx.x;
    if (tid == 0) s_base = 0;
    __syncthreads();
    int nch = (n + 1023) >> 10;
    for (int ch = 0; ch < nch; ch++) {
        int i = (ch << 10) + tid;
        int v = (i < n) ? in[i] : 0;
        sd[tid] = v;
        __syncthreads();
        for (int d = 1; d < 1024; d <<= 1) {
            int t = (tid >= d) ? sd[tid - d] : 0;
            __syncthreads();
            sd[tid] += t;
            __syncthreads();
        }
        int excl = s_base + sd[tid] - v;
        if (i < n) {
            out[i] = excl;
            if (out2) out2[i] = excl;
        }
        __syncthreads();                 // everyone done reading s_base & sd
        if (tid == 1023) s_base += sd[1023];
        __syncthreads();
    }
    if (writeTotal && tid == 0) out[n] = s_base;
}

__global__ void k_scan_cnt()  { scan_dev(g_cnt,  g_off,  g_cur, CC,    1); }
__global__ void k_scan_bsum() { scan_dev(g_bsum, g_boff, 0,     NB_BM, 0); }

// Scatter src ids into cluster-sorted order
__global__ void k_scatter(const int* __restrict__ ei) {
    int e = blockIdx.x * blockDim.x + threadIdx.x;
    if (e >= EE) return;
    int s = ei[e];
    int c = ei[EE + e] >> 2;
    int p = atomicAdd(&g_cur[c], 1);
    g_srcsorted[p] = s;
}

// Per-cluster small outputs: new_pos, residual r, new_batch
__global__ void k_cluster(const float* __restrict__ pos, const int* __restrict__ batch,
                          float* __restrict__ dout) {
    int c = blockIdx.x * blockDim.x + threadIdx.x;
    if (c >= CC) return;
    int base = c * 4;
    float px[4], py[4], pz[4];
    float sx = 0.f, sy = 0.f, sz = 0.f;
    #pragma unroll
    for (int i = 0; i < 4; i++) {
        px[i] = pos[(base + i) * 3 + 0];
        py[i] = pos[(base + i) * 3 + 1];
        pz[i] = pos[(base + i) * 3 + 2];
        sx += px[i]; sy += py[i]; sz += pz[i];
    }
    float nx = sx * 0.25f, ny = sy * 0.25f, nz = sz * 0.25f;
    dout[NP_OFF + c * 3 + 0] = nx;
    dout[NP_OFF + c * 3 + 1] = ny;
    dout[NP_OFF + c * 3 + 2] = nz;
    float rx = 0.f, ry = 0.f, rz = 0.f;
    #pragma unroll
    for (int i = 0; i < 4; i++) {
        rx += px[i] - nx; ry += py[i] - ny; rz += pz[i] - nz;
    }
    g_r[c * 3 + 0] = rx; g_r[c * 3 + 1] = ry; g_r[c * 3 + 2] = rz;
    int b = batch[base];
    #pragma unroll
    for (int i = 1; i < 4; i++) { int v = batch[base + i]; b = (v > b) ? v : b; }
    dout[NB_OFF + c] = (float)b;
}

// One block per cluster: gather-sum x rows of incoming edges, fused 128x128 GEMM epilogue
__global__ void __launch_bounds__(128) k_pool(const float* __restrict__ x,
                                              const float* __restrict__ Wgattr,
                                              float* __restrict__ dout) {
    __shared__ int   sidx[128];
    __shared__ float svec[128];
    int c = blockIdx.x;
    int tid = threadIdx.x;
    int start = g_off[c], end = g_off[c + 1];
    float a0 = 0.f, a1 = 0.f, a2 = 0.f, a3 = 0.f;
    for (int p = start; p < end; p += 128) {
        int nl = min(128, end - p);
        __syncthreads();
        if (tid < nl) sidx[tid] = g_srcsorted[p + tid];
        __syncthreads();
        int r = 0;
        for (; r + 4 <= nl; r += 4) {
            a0 += x[sidx[r + 0] * 128 + tid];
            a1 += x[sidx[r + 1] * 128 + tid];
            a2 += x[sidx[r + 2] * 128 + tid];
            a3 += x[sidx[r + 3] * 128 + tid];
        }
        for (; r < nl; r++) a0 += x[sidx[r] * 128 + tid];
    }
    svec[tid] = (a0 + a1) + (a2 + a3);
    __syncthreads();
    float acc = 0.0f;
    #pragma unroll 8
    for (int t = 0; t < 128; t++) acc += svec[t] * g_Wcomb[t * 128 + tid];
    float ea0 = g_aggea[c * 3 + 0], ea1 = g_aggea[c * 3 + 1], ea2 = g_aggea[c * 3 + 2];
    acc += ea0 * g_Wecomb[0 * 128 + tid] + ea1 * g_Wecomb[1 * 128 + tid] + ea2 * g_Wecomb[2 * 128 + tid];
    float r0 = g_r[c * 3 + 0], r1 = g_r[c * 3 + 1], r2 = g_r[c * 3 + 2];
    acc += r0 * Wgattr[0 * 128 + tid] + r1 * Wgattr[1 * 128 + tid] + r2 * Wgattr[2 * 128 + tid];
    dout[XN_OFF + c * 128 + tid] = 0.25f * acc;
}

// Bitmap popcount per block of 4096 words
__global__ void k_bsum() {
    __shared__ int sd[256];
    int tid = threadIdx.x, b = blockIdx.x;
    int base = b * 4096 + tid * 16;
    int cnt = 0;
    if (base + 16 <= BITWORDS) {
        const uint4* p = (const uint4*)(g_bitmap + base);
        #pragma unroll
        for (int k = 0; k < 4; k++) {
            uint4 v = p[k];
            cnt += __popc(v.x) + __popc(v.y) + __popc(v.z) + __popc(v.w);
        }
    } else {
        for (int k = 0; k < 16; k++) {
            int wi = base + k;
            if (wi < BITWORDS) cnt += __popc(g_bitmap[wi]);
        }
    }
    sd[tid] = cnt;
    __syncthreads();
    for (int d = 128; d > 0; d >>= 1) {
        if (tid < d) sd[tid] += sd[tid + d];
        __syncthreads();
    }
    if (tid == 0) g_bsum[b] = sd[0];
}

// Ordered emit of set bits = sorted unique enc values -> edge index + edge attr
__global__ void k_emit(float* __restrict__ dout) {
    __shared__ int sd[256];
    int tid = threadIdx.x, b = blockIdx.x;
    int wbase = b * 4096 + tid * 16;
    unsigned w[16];
    int cnt = 0;
    if (wbase + 16 <= BITWORDS) {
        const uint4* p = (const uint4*)(g_bitmap + wbase);
        #pragma unroll
        for (int k = 0; k < 4; k++) {
            uint4 v = p[k];
            w[4 * k + 0] = v.x; w[4 * k + 1] = v.y; w[4 * k + 2] = v.z; w[4 * k + 3] = v.w;
        }
    } else {
        #pragma unroll
        for (int k = 0; k < 16; k++) {
            int wi = wbase + k;
            w[k] = (wi < BITWORDS) ? g_bitmap[wi] : 0u;
        }
    }
    #pragma unroll
    for (int k = 0; k < 16; k++) cnt += __popc(w[k]);
    sd[tid] = cnt;
    __syncthreads();
    for (int d = 1; d < 256; d <<= 1) {
        int t = (tid >= d) ? sd[tid - d] : 0;
        __syncthreads();
        sd[tid] += t;
        __syncthreads();
    }
    int pos = g_boff[b] + sd[tid] - cnt;
    float* e0 = dout + EI0_OFF;
    float* e1 = dout + EI1_OFF;
    float* eat = dout + EAT_OFF;
    const float* np = dout + NP_OFF;
    for (int k = 0; k < 16; k++) {
        unsigned ww = w[k];
        int encbase = (wbase + k) << 5;
        while (ww) {
            int bit = __ffs(ww) - 1;
            ww &= ww - 1;
            int enc = encbase + bit;
            int a = enc / CC;
            int d2 = enc - a * CC;
            e0[pos] = (float)a;
            e1[pos] = (float)d2;
            eat[pos * 3 + 0] = np[d2 * 3 + 0] - np[a * 3 + 0];
            eat[pos * 3 + 1] = np[d2 * 3 + 1] - np[a * 3 + 1];
            eat[pos * 3 + 2] = np[d2 * 3 + 2] - np[a * 3 + 2];
            pos++;
        }
    }
}

// ---------------- launch ----------------
extern "C" void kernel_launch(void* const* d_in, const int* in_sizes, int n_in,
                              void* d_out, int out_size) {
    const float* x      = (const float*)d_in[0];
    const float* pos    = (const float*)d_in[1];
    const int*   ei     = (const int*)  d_in[2];
    const float* ea     = (const float*)d_in[3];
    const int*   batch  = (const int*)  d_in[4];
    const float* Wconv  = (const float*)d_in[5];
    const float* Wedge  = (const float*)d_in[6];
    // d_in[7] = D_bloom : dead code in the reference, unused
    const float* Wg     = (const float*)d_in[8];
    const float* Wgattr = (const float*)d_in[9];
    float* out = (float*)d_out;

    k_zero<<<2048, 256>>>(out);
    k_wcomb<<<131, 128>>>(Wconv, Wedge, Wg);
    k_edge1<<<(EE + 255) / 256, 256>>>(ei, ea);
    k_scan_cnt<<<1, 1024>>>();
    k_scatter<<<(EE + 255) / 256, 256>>>(ei);
    k_cluster<<<(CC + 255) / 256, 256>>>(pos, batch, out);
    k_pool<<<CC, 128>>>(x, Wgattr, out);
    k_bsum<<<NB_BM, 256>>>();
    k_scan_bsum<<<1, 1024>>>();
    k_emit<<<NB_BM, 256>>>(out);
}

// round 6
// speedup vs baseline: 1.2555x; 1.2555x over previous
#include <cuda_runtime.h>
#include <cuda_fp16.h>

// Problem constants
#define NN      100000
#define EE      1600000
#define CC      25000          // N / PF
#define KDIM    136            // 128 svec + 3 ea + 3 r + 2 pad
#define BITWORDS 19531250      // C*C / 32 (exact)
#define NB_BM   4769           // ceil(BITWORDS / 4096)

// Output layout (float32, flattened tuple in return order)
#define XN_OFF  0
#define NP_OFF  3200000
#define EI0_OFF 3275000
#define EI1_OFF 4875000
#define EAT_OFF 6475000
#define NB_OFF  11275000

// ---------------- static device scratch ----------------
__device__ __align__(16) unsigned g_bitmap[BITWORDS];   // 78.1 MB
__device__ __align__(16) int   g_cnt[CC];
__device__ __align__(16) int   g_off[CC + 4];
__device__ __align__(16) int   g_cur[CC];
__device__ __align__(16) int4  g_scat[EE];              // (src, ea0, ea1, ea2) cluster-sorted
__device__ __align__(16) __half g_xh[NN * 128];         // fp16 copy of x
__device__ __align__(16) float g_svec[CC * KDIM];       // per-cluster GEMM input rows
__device__ __align__(16) float g_Wext[KDIM * 128];      // [Wconv_feat@Wg ; Wedge_feat@Wg ; Wgattr ; 0]
__device__ unsigned long long g_state[NB_BM];           // decoupled-lookback state
__device__ int g_total;

// ---------------- kernels ----------------

// Zero bitmap/counters/state + convert x to fp16
__global__ void k_zero(const float* __restrict__ x) {
    int tid = blockIdx.x * blockDim.x + threadIdx.x;
    int stride = gridDim.x * blockDim.x;
    uint4 z4 = make_uint4(0u, 0u, 0u, 0u);
    uint4* bm4 = (uint4*)g_bitmap;
    const int n4 = BITWORDS / 4;            // 4,882,812 (covers 19,531,248 words)
    for (int i = tid; i < n4; i += stride) bm4[i] = z4;
    if (tid < 2) g_bitmap[19531248 + tid] = 0u;
    for (int i = tid; i < CC; i += stride) g_cnt[i] = 0;
    for (int i = tid; i < NB_BM; i += stride) g_state[i] = 0ull;
    // fp16 conversion: 3.2M float4
    const float4* x4 = (const float4*)x;
    uint2* xh2 = (uint2*)g_xh;
    for (int i = tid; i < NN * 32; i += stride) {
        float4 v = x4[i];
        __half2 a = __floats2half2_rn(v.x, v.y);
        __half2 b = __floats2half2_rn(v.z, v.w);
        xh2[i] = make_uint2(*(unsigned*)&a, *(unsigned*)&b);
    }
}

// Weight folding + per-cluster small outputs (new_pos, residual->svec, new_batch)
__global__ void k_prep(const float* __restrict__ Wconv, const float* __restrict__ Wedge,
                       const float* __restrict__ Wg, const float* __restrict__ Wgattr,
                       const float* __restrict__ pos, const int* __restrict__ batch,
                       float* __restrict__ dout) {
    int b = blockIdx.x;
    int j = threadIdx.x;                    // 0..127
    if (b < 128) {                          // Wconv[:,16:] @ Wg  -> rows 0..127
        float acc = 0.0f;
        #pragma unroll 8
        for (int t = 0; t < 128; t++) acc += Wconv[b * 144 + 16 + t] * Wg[t * 128 + j];
        g_Wext[b * 128 + j] = acc;
    } else if (b < 131) {                   // Wedge[:,16:] @ Wg  -> rows 128..130
        int a = b - 128;
        float acc = 0.0f;
        #pragma unroll 8
        for (int t = 0; t < 128; t++) acc += Wedge[a * 144 + 16 + t] * Wg[t * 128 + j];
        g_Wext[b * 128 + j] = acc;
    } else if (b < 134) {                   // Wgattr -> rows 131..133
        g_Wext[b * 128 + j] = Wgattr[(b - 131) * 128 + j];
    } else if (b < 136) {                   // pad rows 134..135
        g_Wext[b * 128 + j] = 0.0f;
    } else {                                // cluster blocks
        int c = (b - 136) * 128 + j;
        if (c >= CC) return;
        int base = c * 4;
        float px[4], py[4], pz[4];
        float sx = 0.f, sy = 0.f, sz = 0.f;
        #pragma unroll
        for (int i = 0; i < 4; i++) {
            px[i] = pos[(base + i) * 3 + 0];
            py[i] = pos[(base + i) * 3 + 1];
            pz[i] = pos[(base + i) * 3 + 2];
            sx += px[i]; sy += py[i]; sz += pz[i];
        }
        float nx = sx * 0.25f, ny = sy * 0.25f, nz = sz * 0.25f;
        dout[NP_OFF + c * 3 + 0] = nx;
        dout[NP_OFF + c * 3 + 1] = ny;
        dout[NP_OFF + c * 3 + 2] = nz;
        float rx = 0.f, ry = 0.f, rz = 0.f;
        #pragma unroll
        for (int i = 0; i < 4; i++) { rx += px[i] - nx; ry += py[i] - ny; rz += pz[i] - nz; }
        g_svec[c * KDIM + 131] = rx;
        g_svec[c * KDIM + 132] = ry;
        g_svec[c * KDIM + 133] = rz;
        int bm = batch[base];
        #pragma unroll
        for (int i = 1; i < 4; i++) { int v = batch[base + i]; bm = (v > bm) ? v : bm; }
        dout[NB_OFF + c] = (float)bm;
    }
}

// Edge pass 1: histogram by dst-cluster + bitmap bit for enc
__global__ void k_edge1(const int* __restrict__ ei) {
    int e = blockIdx.x * blockDim.x + threadIdx.x;
    if (e >= EE) return;
    int s = ei[e];
    int c = ei[EE + e] >> 2;
    atomicAdd(&g_cnt[c], 1);
    int enc = (s >> 2) * CC + c;
    atomicOr(&g_bitmap[enc >> 5], 1u << (enc & 31));
}

// Fast single-block scan: 1024 threads x 4 elems/chunk, warp-shuffle based
__global__ void k_scan() {
    __shared__ int warp_sums[32];
    __shared__ int s_base;
    const int tid = threadIdx.x;
    const int lane = tid & 31, wid = tid >> 5;
    if (tid == 0) { s_base = 0; g_off[CC] = EE; }
    __syncthreads();
    const int n = CC;
    const int nch = (n + 4095) / 4096;      // 7
    for (int chunk = 0; chunk < nch; chunk++) {
        int base = chunk * 4096 + tid * 4;
        int4 v = make_int4(0, 0, 0, 0);
        if (base + 3 < n) v = *(const int4*)(g_cnt + base);
        int t0 = v.x, t1 = t0 + v.y, t2 = t1 + v.z, t3 = t2 + v.w;
        int incl = t3;
        #pragma unroll
        for (int d = 1; d < 32; d <<= 1) {
            int y = __shfl_up_sync(0xffffffffu, incl, d);
            if (lane >= d) incl += y;
        }
        if (lane == 31) warp_sums[wid] = incl;
        __syncthreads();
        if (wid == 0) {
            int w = warp_sums[lane];
            int wi = w;
            #pragma unroll
            for (int d = 1; d < 32; d <<= 1) {
                int y = __shfl_up_sync(0xffffffffu, wi, d);
                if (lane >= d) wi += y;
            }
            warp_sums[lane] = wi - w;       // exclusive warp offset
        }
        __syncthreads();
        int thread_excl = s_base + warp_sums[wid] + (incl - t3);
        if (base + 3 < n) {
            int4 e4 = make_int4(thread_excl, thread_excl + t0, thread_excl + t1, thread_excl + t2);
            *(int4*)(g_off + base) = e4;
            *(int4*)(g_cur + base) = e4;
        }
        __syncthreads();
        if (tid == 1023) s_base = thread_excl + t3;
        __syncthreads();
    }
}

// Scatter (src, ea) into cluster-sorted order
__global__ void k_scatter(const int* __restrict__ ei, const float* __restrict__ ea) {
    int e = blockIdx.x * blockDim.x + threadIdx.x;
    if (e >= EE) return;
    int s = ei[e];
    int c = ei[EE + e] >> 2;
    float a0 = ea[e * 3 + 0], a1 = ea[e * 3 + 1], a2 = ea[e * 3 + 2];
    int p = atomicAdd(&g_cur[c], 1);
    g_scat[p] = make_int4(s, __float_as_int(a0), __float_as_int(a1), __float_as_int(a2));
}

// One block per cluster: fp16 gather-sum of x rows + ea sum -> g_svec row
__global__ void __launch_bounds__(128) k_pool() {
    __shared__ int   sidx[128];
    __shared__ float sacc[4][128];
    __shared__ float sea[3][4];
    const int c = blockIdx.x;
    const int tid = threadIdx.x;
    const int g = tid >> 5, l = tid & 31;
    const int start = g_off[c], end = g_off[c + 1];
    const uint2* xp2 = (const uint2*)g_xh;   // row stride 32 uint2 (128 halfs)
    float fx0 = 0.f, fx1 = 0.f, fx2 = 0.f, fx3 = 0.f;
    float ex = 0.f, ey = 0.f, ez = 0.f;
    for (int p = start; p < end; p += 128) {
        int nl = min(128, end - p);
        __syncthreads();
        if (tid < nl) {
            int4 q = g_scat[p + tid];
            sidx[tid] = q.x;
            ex += __int_as_float(q.y);
            ey += __int_as_float(q.z);
            ez += __int_as_float(q.w);
        }
        __syncthreads();
        int r = 0;
        for (; r + 8 <= nl; r += 8) {
            int ra = sidx[r + g], rb = sidx[r + g + 4];
            uint2 ua = xp2[ra * 32 + l];
            uint2 ub = xp2[rb * 32 + l];
            __half2 h0 = *(__half2*)&ua.x, h1 = *(__half2*)&ua.y;
            __half2 h2 = *(__half2*)&ub.x, h3 = *(__half2*)&ub.y;
            float2 f0 = __half22float2(h0), f1 = __half22float2(h1);
            float2 f2 = __half22float2(h2), f3 = __half22float2(h3);
            fx0 += f0.x + f2.x; fx1 += f0.y + f2.y;
            fx2 += f1.x + f3.x; fx3 += f1.y + f3.y;
        }
        for (; r + 4 <= nl; r += 4) {
            int ra = sidx[r + g];
            uint2 ua = xp2[ra * 32 + l];
            __half2 h0 = *(__half2*)&ua.x, h1 = *(__half2*)&ua.y;
            float2 f0 = __half22float2(h0), f1 = __half22float2(h1);
            fx0 += f0.x; fx1 += f0.y; fx2 += f1.x; fx3 += f1.y;
        }
        int rem = nl - r;
        if (g < rem) {
            int ra = sidx[r + g];
            uint2 ua = xp2[ra * 32 + l];
            __half2 h0 = *(__half2*)&ua.x, h1 = *(__half2*)&ua.y;
            float2 f0 = __half22float2(h0), f1 = __half22float2(h1);
            fx0 += f0.x; fx1 += f0.y; fx2 += f1.x; fx3 += f1.y;
        }
    }
    sacc[g][4 * l + 0] = fx0;
    sacc[g][4 * l + 1] = fx1;
    sacc[g][4 * l + 2] = fx2;
    sacc[g][4 * l + 3] = fx3;
    #pragma unroll
    for (int d = 16; d; d >>= 1) {
        ex += __shfl_down_sync(0xffffffffu, ex, d);
        ey += __shfl_down_sync(0xffffffffu, ey, d);
        ez += __shfl_down_sync(0xffffffffu, ez, d);
    }
    if (l == 0) { sea[0][g] = ex; sea[1][g] = ey; sea[2][g] = ez; }
    __syncthreads();
    g_svec[c * KDIM + tid] = sacc[0][tid] + sacc[1][tid] + sacc[2][tid] + sacc[3][tid];
    if (tid < 3) g_svec[c * KDIM + 128 + tid] = sea[tid][0] + sea[tid][1] + sea[tid][2] + sea[tid][3];
    if (tid < 2) g_svec[c * KDIM + 134 + tid] = 0.0f;
}

// Register-tiled GEMM: x_new[25000][128] = 0.25 * svec[25000][136] @ Wext[136][128]
__global__ void __launch_bounds__(256) k_gemm(float* __restrict__ dout) {
    __shared__ float sS[8][128];
    __shared__ float sW[8][128];
    const int tid = threadIdx.x;
    const int ty = tid >> 4, tx = tid & 15;
    const int row0 = blockIdx.x * 128;
    float acc[8][8];
    #pragma unroll
    for (int i = 0; i < 8; i++)
        #pragma unroll
        for (int j = 0; j < 8; j++) acc[i][j] = 0.0f;

    const int rl = tid >> 1, kq = (tid & 1) * 4;
    const int kk = tid >> 5, c4 = (tid & 31) * 4;
    for (int k0 = 0; k0 < KDIM; k0 += 8) {
        int row = row0 + rl;
        float4 v = make_float4(0.f, 0.f, 0.f, 0.f);
        if (row < CC) v = *(const float4*)(g_svec + row * KDIM + k0 + kq);
        float4 wv = *(const float4*)(g_Wext + (k0 + kk) * 128 + c4);
        __syncthreads();
        sS[kq + 0][rl] = v.x; sS[kq + 1][rl] = v.y; sS[kq + 2][rl] = v.z; sS[kq + 3][rl] = v.w;
        *(float4*)&sW[kk][c4] = wv;
        __syncthreads();
        #pragma unroll
        for (int q = 0; q < 8; q++) {
            float a[8], b[8];
            *(float4*)&a[0] = *(float4*)&sS[q][ty * 8];
            *(float4*)&a[4] = *(float4*)&sS[q][ty * 8 + 4];
            *(float4*)&b[0] = *(float4*)&sW[q][tx * 8];
            *(float4*)&b[4] = *(float4*)&sW[q][tx * 8 + 4];
            #pragma unroll
            for (int i = 0; i < 8; i++)
                #pragma unroll
                for (int j = 0; j < 8; j++) acc[i][j] += a[i] * b[j];
        }
    }
    #pragma unroll
    for (int i = 0; i < 8; i++) {
        int row = row0 + ty * 8 + i;
        if (row < CC) {
            float4 o0 = make_float4(acc[i][0] * 0.25f, acc[i][1] * 0.25f, acc[i][2] * 0.25f, acc[i][3] * 0.25f);
            float4 o1 = make_float4(acc[i][4] * 0.25f, acc[i][5] * 0.25f, acc[i][6] * 0.25f, acc[i][7] * 0.25f);
            *(float4*)(dout + XN_OFF + row * 128 + tx * 8) = o0;
            *(float4*)(dout + XN_OFF + row * 128 + tx * 8 + 4) = o1;
        }
    }
}

// Single-pass ordered emit of set bits (decoupled lookback) -> edge index + attr
__global__ void __launch_bounds__(256) k_emit(float* __restrict__ dout) {
    __shared__ int warp_sums[8];
    __shared__ int s_prefix;
    const int tid = threadIdx.x, b = blockIdx.x;
    const int lane = tid & 31, wid = tid >> 5;
    const int wbase = b * 4096 + tid * 16;
    unsigned w[16];
    if (wbase + 16 <= BITWORDS) {
        const uint4* p = (const uint4*)(g_bitmap + wbase);
        #pragma unroll
        for (int k = 0; k < 4; k++) {
            uint4 v = p[k];
            w[4 * k + 0] = v.x; w[4 * k + 1] = v.y; w[4 * k + 2] = v.z; w[4 * k + 3] = v.w;
        }
    } else {
        #pragma unroll
        for (int k = 0; k < 16; k++) {
            int wi = wbase + k;
            w[k] = (wi < BITWORDS) ? g_bitmap[wi] : 0u;
        }
    }
    int cnt = 0;
    #pragma unroll
    for (int k = 0; k < 16; k++) cnt += __popc(w[k]);
    int incl = cnt;
    #pragma unroll
    for (int d = 1; d < 32; d <<= 1) {
        int y = __shfl_up_sync(0xffffffffu, incl, d);
        if (lane >= d) incl += y;
    }
    if (lane == 31) warp_sums[wid] = incl;
    __syncthreads();
    if (tid == 0) {
        int run = 0;
        #pragma unroll
        for (int k = 0; k < 8; k++) { int t = warp_sums[k]; warp_sums[k] = run; run += t; }
        int block_total = run;
        if (b == 0) {
            s_prefix = 0;
            atomicExch(&g_state[0], (2ull << 32) | (unsigned)block_total);
        } else {
            atomicExch(&g_state[b], (1ull << 32) | (unsigned)block_total);
            int run2 = 0;
            int j = b - 1;
            while (1) {
                unsigned long long s;
                do { s = atomicAdd(&g_state[j], 0ull); } while ((s >> 32) == 0ull);
                run2 += (int)(unsigned)s;
                if ((s >> 32) == 2ull) break;
                j--;
            }
            s_prefix = run2;
            atomicExch(&g_state[b], (2ull << 32) | (unsigned)(run2 + block_total));
            if (b == NB_BM - 1) g_total = run2 + block_total;
        }
        if (b == 0 && NB_BM == 1) g_total = block_total;
    }
    __syncthreads();
    int pos = s_prefix + warp_sums[wid] + (incl - cnt);
    float* e0 = dout + EI0_OFF;
    float* e1 = dout + EI1_OFF;
    float* eat = dout + EAT_OFF;
    const float* np = dout + NP_OFF;
    for (int k = 0; k < 16; k++) {
        unsigned ww = w[k];
        int encbase = (wbase + k) << 5;
        while (ww) {
            int bit = __ffs(ww) - 1;
            ww &= ww - 1;
            int enc = encbase + bit;
            int a = enc / CC;
            int d2 = enc - a * CC;
            e0[pos] = (float)a;
            e1[pos] = (float)d2;
            eat[pos * 3 + 0] = np[d2 * 3 + 0] - np[a * 3 + 0];
            eat[pos * 3 + 1] = np[d2 * 3 + 1] - np[a * 3 + 1];
            eat[pos * 3 + 2] = np[d2 * 3 + 2] - np[a * 3 + 2];
            pos++;
        }
    }
}

// Zero the fill tail [g_total, E) of the edge outputs
__global__ void k_tail(float* __restrict__ dout) {
    int i = blockIdx.x * blockDim.x + threadIdx.x;
    int total = g_total;
    if (i >= total && i < EE) {
        dout[EI0_OFF + i] = 0.0f;
        dout[EI1_OFF + i] = 0.0f;
        dout[EAT_OFF + 3 * i + 0] = 0.0f;
        dout[EAT_OFF + 3 * i + 1] = 0.0f;
        dout[EAT_OFF + 3 * i + 2] = 0.0f;
    }
}

// ---------------- launch ----------------
extern "C" void kernel_launch(void* const* d_in, const int* in_sizes, int n_in,
                              void* d_out, int out_size) {
    const float* x      = (const float*)d_in[0];
    const float* pos    = (const float*)d_in[1];
    const int*   ei     = (const int*)  d_in[2];
    const float* ea     = (const float*)d_in[3];
    const int*   batch  = (const int*)  d_in[4];
    const float* Wconv  = (const float*)d_in[5];
    const float* Wedge  = (const float*)d_in[6];
    // d_in[7] = D_bloom : dead in the reference
    const float* Wg     = (const float*)d_in[8];
    const float* Wgattr = (const float*)d_in[9];
    float* out = (float*)d_out;

    k_zero<<<2048, 256>>>(x);
    k_prep<<<136 + (CC + 127) / 128, 128>>>(Wconv, Wedge, Wg, Wgattr, pos, batch, out);
    k_edge1<<<(EE + 255) / 256, 256>>>(ei);
    k_scan<<<1, 1024>>>();
    k_scatter<<<(EE + 255) / 256, 256>>>(ei, ea);
    k_pool<<<CC, 128>>>();
    k_gemm<<<(CC + 127) / 128, 256>>>(out);
    k_emit<<<NB_BM, 256>>>(out);
    k_tail<<<(EE + 255) / 256, 256>>>(out);
}